// round 16
// baseline (speedup 1.0000x reference)
#include <cuda_runtime.h>

#define NN   50000
#define NE   1200000
#define NG   64
#define FN   128
#define FE   32
#define HD   64
#define HIDD 128
#define NL   3
#define NPROBE 3125

typedef unsigned long long ull;

// ---------------- device scratch ----------------
__device__ __align__(16) float g_ea[(size_t)NE * HD];      // edge embeddings fp32, dst-sorted order
__device__ __align__(16) float g_h[NN * HD];               // node state
__device__ __align__(16) float g_xin[NN * HD];             // conv input (gather source)
__device__ __align__(16) float g_agg[NPROBE * HD];         // probe output (dead)
__device__ int  g_cnt[NN];                                 // in-degree histogram (zeroed by setup for next call)
__device__ int  g_off[NN + 1];                             // CSR offsets
__device__ int  g_cur[NN];                                 // running scatter cursor
__device__ int  g_srcp[NE];                                // src node per sorted slot
__device__ int  g_epos[NE];                                // sorted slot for edge e
__device__ unsigned int g_pool[NG * HD];                   // encoded max-pool
__device__ __align__(16) float g_w1t[NL][HD][HIDD];        // conv_w1^T  [l][k][j]
__device__ __align__(16) float g_w2t[NL][HIDD][HD];        // conv_w2^T  [l][j][o]

__device__ __forceinline__ unsigned fenc(float f) {
    unsigned u = __float_as_uint(f);
    return (u & 0x80000000u) ? ~u : (u | 0x80000000u);
}
__device__ __forceinline__ float fdec(unsigned u) {
    return (u & 0x80000000u) ? __uint_as_float(u & 0x7fffffffu) : __uint_as_float(~u);
}

__device__ __forceinline__ void warp_reduce2(float& s, float& s2) {
#pragma unroll
    for (int o = 16; o > 0; o >>= 1) {
        s  += __shfl_xor_sync(0xffffffffu, s,  o);
        s2 += __shfl_xor_sync(0xffffffffu, s2, o);
    }
}

// ---- packed f32x2 helpers (FFMA2 on sm_103a) ----
__device__ __forceinline__ ull f2pack(float lo, float hi) {
    ull r; asm("mov.b64 %0,{%1,%2};" : "=l"(r) : "f"(lo), "f"(hi)); return r;
}
__device__ __forceinline__ void f2unpack(ull v, float& lo, float& hi) {
    asm("mov.b64 {%0,%1},%2;" : "=f"(lo), "=f"(hi) : "l"(v));
}
__device__ __forceinline__ ull ffma2(ull a, ull b, ull c) {
    ull d; asm("fma.rn.f32x2 %0,%1,%2,%3;" : "=l"(d) : "l"(a), "l"(b), "l"(c)); return d;
}
__device__ __forceinline__ ull addf2(ull a, ull b) {
    ull d; asm("add.rn.f32x2 %0,%1,%2;" : "=l"(d) : "l"(a), "l"(b)); return d;
}

// ---------------- CSR build ----------------
__global__ void k_hist(const int* __restrict__ dst) {
    int e = blockIdx.x * blockDim.x + threadIdx.x;
    if (e < NE) atomicAdd(&g_cnt[dst[e]], 1);
}

__global__ void k_scan() {
    __shared__ int part[1024];
    int t = threadIdx.x;
    const int per = (NN + 1023) / 1024;   // 49
    int base = t * per;
    int s = 0;
#pragma unroll 4
    for (int i = 0; i < per; i++) {
        int b = base + i;
        if (b < NN) s += g_cnt[b];
    }
    part[t] = s;
    __syncthreads();
    for (int o = 1; o < 1024; o <<= 1) {
        int v = (t >= o) ? part[t - o] : 0;
        __syncthreads();
        part[t] += v;
        __syncthreads();
    }
    int run = part[t] - s;   // exclusive prefix
    for (int i = 0; i < per; i++) {
        int b = base + i;
        if (b < NN) {
            g_off[b] = run;
            g_cur[b] = run;
            run += g_cnt[b];
        }
    }
    if (t == 1023) g_off[NN] = part[1023];
}

__global__ void k_scatter(const int* __restrict__ src, const int* __restrict__ dst) {
    int e = blockIdx.x * blockDim.x + threadIdx.x;
    if (e >= NE) return;
    int d = dst[e];
    int p = atomicAdd(&g_cur[d], 1);
    g_srcp[p] = src[e];
    g_epos[e] = p;
}

// ---------------- aggregation core: 8-wide pipeline, split accumulators ----------------
// Callers must grant generous regs (launch_bounds minBlocks=2 -> 128 max) or the
// 16 in-flight loads get serialized by ptxas (R11: 40 regs -> MLP=1; R15: 64 -> MLP~4).
__device__ __forceinline__ void agg_node(int n, int j0, int j1, float t,
                                         float& o0, float& o1, int lane) {
    const float2* ea2  = (const float2*)g_ea;
    const float2* xin2 = (const float2*)g_xin;
    int nk = j1 - j0;
    float d0a = 0.f, d1a = 0.f, w0a = 0.f, w1a = 0.f;
    float d0b = 0.f, d1b = 0.f, w0b = 0.f, w1b = 0.f;
    for (int base = 0; base < nk; base += 32) {
        int cn = nk - base; if (cn > 32) cn = 32;
        int sv = (lane < cn) ? __ldg(&g_srcp[j0 + base + lane]) : 0;
        int kk = 0;
        for (; kk + 8 <= cn; kk += 8) {
            int s[8];
#pragma unroll
            for (int u = 0; u < 8; u++) s[u] = __shfl_sync(0xffffffffu, sv, kk + u);
            float2 ev[8], xv[8];
            size_t eb = (size_t)(j0 + base + kk) * (HD / 2) + lane;
#pragma unroll
            for (int u = 0; u < 8; u++) ev[u] = __ldcs(ea2 + eb + (size_t)u * (HD / 2));
#pragma unroll
            for (int u = 0; u < 8; u++) xv[u] = __ldg(xin2 + (size_t)s[u] * (HD / 2) + lane);
#pragma unroll
            for (int u = 0; u < 8; u++) {
                float m0 = fmaxf(xv[u].x + ev[u].x, 0.0f) + 1e-7f;
                float m1 = fmaxf(xv[u].y + ev[u].y, 0.0f) + 1e-7f;
                float a0 = __expf(m0 * t), a1 = __expf(m1 * t);
                if (u & 1) {
                    d0b += a0; d1b += a1;
                    w0b = fmaf(m0, a0, w0b); w1b = fmaf(m1, a1, w1b);
                } else {
                    d0a += a0; d1a += a1;
                    w0a = fmaf(m0, a0, w0a); w1a = fmaf(m1, a1, w1a);
                }
            }
        }
        for (; kk < cn; kk++) {
            int s = __shfl_sync(0xffffffffu, sv, kk);
            float2 ev = __ldcs(ea2 + (size_t)(j0 + base + kk) * (HD / 2) + lane);
            float2 xv = __ldg(xin2 + (size_t)s * (HD / 2) + lane);
            float m0 = fmaxf(xv.x + ev.x, 0.0f) + 1e-7f;
            float m1 = fmaxf(xv.y + ev.y, 0.0f) + 1e-7f;
            float a0 = __expf(m0 * t), a1 = __expf(m1 * t);
            d0a += a0; d1a += a1;
            w0a = fmaf(m0, a0, w0a); w1a = fmaf(m1, a1, w1a);
        }
    }
    float d0 = d0a + d0b, d1 = d1a + d1b;
    float w0 = w0a + w0b, w1v = w1a + w1b;
    float2 xself = xin2[(size_t)n * (HD / 2) + lane];
    o0 = w0  / (d0 + 1e-16f) + xself.x;
    o1 = w1v / (d1 + 1e-16f) + xself.y;
}

// ---------------- PROBE: agg only, 1/16 of nodes, dead output (ncu lands here) ----------------
__global__ void __launch_bounds__(256, 2) k_agg_probe(const float* __restrict__ ct) {
    int warp = threadIdx.x >> 5, lane = threadIdx.x & 31;
    int n = blockIdx.x * 8 + warp;
    if (n >= NPROBE) return;
    float t = __ldg(ct + 1);
    int j0 = __ldg(&g_off[n]), j1 = __ldg(&g_off[n + 1]);
    float o0, o1;
    agg_node(n, j0, j1, t, o0, o1, lane);
    ((float2*)g_agg)[(size_t)n * (HD / 2) + lane] = make_float2(o0, o1);
}

// ---------------- fused setup: transpose + embed (h AND xin) + zero cnt/pool ----------------
__global__ void __launch_bounds__(256) k_setup(
        const float* __restrict__ x, const float* __restrict__ ne_w,
        const float* __restrict__ ne_b,
        const float* __restrict__ cw1, const float* __restrict__ cw2) {
    int gid = blockIdx.x * blockDim.x + threadIdx.x;
    if (gid < NN) g_cnt[gid] = 0;                               // for NEXT call's hist
    else if (gid < NN + NG * HD) g_pool[gid - NN] = 0u;
    else if (gid < NN + NG * HD + NL * HIDD * HD) {
        int i = gid - NN - NG * HD;
        int l = i / (HIDD * HD), r = i % (HIDD * HD);
        int j = r / HD, k = r % HD;
        g_w1t[l][k][j] = cw1[i];
    } else if (gid < NN + NG * HD + 2 * NL * HIDD * HD) {
        int i = gid - NN - NG * HD - NL * HIDD * HD;
        int l = i / (HD * HIDD), r = i % (HD * HIDD);
        int o = r / HIDD, j = r % HIDD;
        g_w2t[l][j][o] = cw2[i];
    }

    __shared__ float wst[FN][HD];
    __shared__ float xsh[8][FN];
    for (int idx = threadIdx.x; idx < FN * HD; idx += blockDim.x) {
        int j = idx & (HD - 1), k = idx >> 6;
        wst[k][j] = ne_w[j * FN + k];
    }
    __syncthreads();
    int warp = threadIdx.x >> 5, lane = threadIdx.x & 31;
    int n = blockIdx.x * 8 + warp;
    if (n >= NN) return;
    ((float4*)xsh[warp])[lane] = ((const float4*)x)[(size_t)n * (FN / 4) + lane];
    __syncwarp();
    float acc0 = ne_b[lane], acc1 = ne_b[lane + 32];
#pragma unroll
    for (int k = 0; k < FN; k++) {
        float xk = xsh[warp][k];
        acc0 = fmaf(xk, wst[k][lane], acc0);
        acc1 = fmaf(xk, wst[k][lane + 32], acc1);
    }
    g_h[n * HD + lane]        = acc0;
    g_h[n * HD + lane + 32]   = acc1;
    g_xin[n * HD + lane]      = acc0;
    g_xin[n * HD + lane + 32] = acc1;
}

// ---------------- edge MLP: transposed-attr staging + per-edge GEMM1 + tiled GEMM2 ----------
// 128 threads = 128 edges per block; NE divisible by 128 (9375 blocks, no tail).
__global__ void __launch_bounds__(128) k_edge_mlp(
        const float* __restrict__ attr,
        const float* __restrict__ w1, const float* __restrict__ b1,
        const float* __restrict__ w2, const float* __restrict__ b2) {
    __shared__ __align__(16) ull w1p[FE][FE / 2];     // 4KB
    __shared__ __align__(16) ull w2p[FE][HD / 2];     // 8KB
    __shared__ __align__(16) ull b1p[FE / 2];
    __shared__ __align__(16) ull b2p[HD / 2];
    __shared__ int posb[128];
    __shared__ __align__(16) float ubuf[FE * 129];    // 16.5KB: aT, then hT, then stage
    float (*aT)[129] = (float(*)[129])ubuf;           // [k][edge], pitch 129 (conflict-free)
    float (*hT)[128] = (float(*)[128])ubuf;           // [hidden j][edge]
    ull* stage = (ull*)ubuf;                          // quarter: 32 rows x 33 ull (8.4KB)

    int tid = threadIdx.x;
    for (int i = tid; i < FE * FE / 2; i += blockDim.x) {
        int k = i / (FE / 2), j2 = i % (FE / 2);
        w1p[k][j2] = f2pack(w1[(2 * j2) * FE + k], w1[(2 * j2 + 1) * FE + k]);
    }
    for (int i = tid; i < FE * HD / 2; i += blockDim.x) {
        int j = i / (HD / 2), i2 = i % (HD / 2);
        w2p[j][i2] = f2pack(w2[(2 * i2) * FE + j], w2[(2 * i2 + 1) * FE + j]);
    }
    if (tid < FE / 2) b1p[tid] = f2pack(b1[2 * tid], b1[2 * tid + 1]);
    if (tid >= 64 && tid < 64 + HD / 2) {
        int i2 = tid - 64;
        b2p[i2] = f2pack(b2[2 * i2], b2[2 * i2 + 1]);
    }
    int eb = blockIdx.x * 128;
    posb[tid] = __ldg(&g_epos[eb + tid]);

    // --- coalesced attr load + conflict-free transposed store ---
    // write bank = (4*k4 + m + e_) mod 32; per instruction (fixed m, i):
    // lanes l: 4*(l&7) + (l>>3) is a bijection on 0..31 -> conflict-free.
    {
        const float4* gsrc = (const float4*)(attr + (size_t)eb * FE);
#pragma unroll
        for (int i = 0; i < 8; i++) {
            int c = tid + i * 128;               // float4 index within block tile
            float4 v = __ldcs(gsrc + c);
            int e_ = c >> 3, k4 = c & 7;
            aT[4 * k4 + 0][e_] = v.x;
            aT[4 * k4 + 1][e_] = v.y;
            aT[4 * k4 + 2][e_] = v.z;
            aT[4 * k4 + 3][e_] = v.w;
        }
    }
    __syncthreads();

    // pull this thread's edge row into registers (lane-consecutive: conflict-free)
    float av[FE];
#pragma unroll
    for (int k = 0; k < FE; k++) av[k] = aT[k][tid];
    __syncthreads();   // attr reads done; ubuf may be overwritten as hT

    // --- GEMM1 (per edge, register-resident) ---
    ull hp[FE / 2];
#pragma unroll
    for (int j2 = 0; j2 < FE / 2; j2++) hp[j2] = b1p[j2];
#pragma unroll
    for (int k = 0; k < FE; k++) {
        ull vkk = f2pack(av[k], av[k]);
#pragma unroll
        for (int j4 = 0; j4 < FE / 4; j4++) {
            ulonglong2 w = *(const ulonglong2*)&w1p[k][2 * j4];
            hp[2 * j4]     = ffma2(vkk, w.x, hp[2 * j4]);
            hp[2 * j4 + 1] = ffma2(vkk, w.y, hp[2 * j4 + 1]);
        }
    }
    // relu -> hT columns (conflict-free: bank = edge lane)
#pragma unroll
    for (int j2 = 0; j2 < FE / 2; j2++) {
        float lo, hi; f2unpack(hp[j2], lo, hi);
        hT[2 * j2][tid]     = fmaxf(lo, 0.0f);
        hT[2 * j2 + 1][tid] = fmaxf(hi, 0.0f);
    }
    __syncthreads();

    // --- GEMM2 (tiled): thread (eg = tid&31 -> edges eg+32n, og = tid>>5 -> outputs 16og..+15)
    int eg = tid & 31, og = tid >> 5;
    ull acc[4][8];   // [n -> edge eg+32n][output pair]
    {
        ulonglong2 bA = *(const ulonglong2*)&b2p[8 * og];
        ulonglong2 bB = *(const ulonglong2*)&b2p[8 * og + 2];
        ulonglong2 bC = *(const ulonglong2*)&b2p[8 * og + 4];
        ulonglong2 bD = *(const ulonglong2*)&b2p[8 * og + 6];
#pragma unroll
        for (int n = 0; n < 4; n++) {
            acc[n][0] = bA.x; acc[n][1] = bA.y; acc[n][2] = bB.x; acc[n][3] = bB.y;
            acc[n][4] = bC.x; acc[n][5] = bC.y; acc[n][6] = bD.x; acc[n][7] = bD.y;
        }
    }
#pragma unroll 2
    for (int k = 0; k < FE; k++) {
        float h0 = hT[k][eg], h1 = hT[k][eg + 32];
        float h2 = hT[k][eg + 64], h3 = hT[k][eg + 96];
        ull a0 = f2pack(h0, h0), a1 = f2pack(h1, h1);
        ull a2 = f2pack(h2, h2), a3 = f2pack(h3, h3);
        ulonglong2 wA = *(const ulonglong2*)&w2p[k][8 * og];
        ulonglong2 wB = *(const ulonglong2*)&w2p[k][8 * og + 2];
        ulonglong2 wC = *(const ulonglong2*)&w2p[k][8 * og + 4];
        ulonglong2 wD = *(const ulonglong2*)&w2p[k][8 * og + 6];
#define G2ROW(n, an)                                                     \
        acc[n][0] = ffma2(an, wA.x, acc[n][0]);                          \
        acc[n][1] = ffma2(an, wA.y, acc[n][1]);                          \
        acc[n][2] = ffma2(an, wB.x, acc[n][2]);                          \
        acc[n][3] = ffma2(an, wB.y, acc[n][3]);                          \
        acc[n][4] = ffma2(an, wC.x, acc[n][4]);                          \
        acc[n][5] = ffma2(an, wC.y, acc[n][5]);                          \
        acc[n][6] = ffma2(an, wD.x, acc[n][6]);                          \
        acc[n][7] = ffma2(an, wD.y, acc[n][7]);
        G2ROW(0, a0) G2ROW(1, a1) G2ROW(2, a2) G2ROW(3, a3)
#undef G2ROW
    }
    __syncthreads();   // GEMM2 hT reads complete before stage aliases ubuf

    // --- staged coalesced scatter-store: 4 quarters of 32 edges ---
#pragma unroll
    for (int qd = 0; qd < 4; qd++) {
#pragma unroll
        for (int q = 0; q < 8; q++)
            stage[(size_t)eg * 33 + 8 * og + q] = acc[qd][q];
        __syncthreads();
#pragma unroll
        for (int p = 0; p < 4; p++) {
            int le = p * 8 + (tid >> 4);   // 0..31
            int ch = tid & 15;             // 16B chunk within row
            ull a = stage[(size_t)le * 33 + 2 * ch];
            ull b = stage[(size_t)le * 33 + 2 * ch + 1];
            int pos = posb[32 * qd + le];
            *(ulonglong2*)(g_ea + (size_t)pos * HD + 4 * ch) = make_ulonglong2(a, b);
        }
        __syncthreads();
    }
}

// ---------------- pre-norm: xin = relu(LN(h)) ----------------
__global__ void k_prep(const float* __restrict__ lng, const float* __restrict__ lnb, int layer) {
    int gid = blockIdx.x * blockDim.x + threadIdx.x;
    int n = gid >> 5, lane = gid & 31;
    if (n >= NN) return;
    float v0 = g_h[n * HD + lane], v1 = g_h[n * HD + lane + 32];
    float s = v0 + v1, s2 = v0 * v0 + v1 * v1;
    warp_reduce2(s, s2);
    float mu = s * (1.0f / HD);
    float var = s2 * (1.0f / HD) - mu * mu;
    float rs = rsqrtf(var + 1e-5f);
    const float* g = lng + layer * HD;
    const float* b = lnb + layer * HD;
    g_xin[n * HD + lane]      = fmaxf((v0 - mu) * rs * g[lane] + b[lane], 0.0f);
    g_xin[n * HD + lane + 32] = fmaxf((v1 - mu) * rs * g[lane + 32] + b[lane + 32], 0.0f);
}

// ---------------- fused layer: 64-node tile, agg + block-cooperative MLP ----------------
union SmemA {
    float xsT[HD][64];                                   // [feat][local node]
    struct { ull red[64][17]; float2 murs[64]; } r;      // aliased AFTER GEMM1 reads done
};

__global__ void __launch_bounds__(256, 2) k_layer(
                        int resid, int layer,
                        const float* __restrict__ cb1, const float* __restrict__ cg,
                        const float* __restrict__ cbn, const float* __restrict__ cb2,
                        const float* __restrict__ ct) {
    __shared__ SmemA sA;
    __shared__ float HT[HIDD][64];                       // [hid][local node]
    int tid = threadIdx.x;
    int warp = tid >> 5, lane = tid & 31;
    int nb = blockIdx.x * 64;
    float t = __ldg(ct + layer);

    // Phase A: 8 warps x 8 nodes, agg core; transposed store
    for (int q = 0; q < 8; q++) {
        int ln = warp * 8 + q;
        int n = nb + ln;
        float o0 = 0.0f, o1 = 0.0f;
        if (n < NN) {
            int j0 = __ldg(&g_off[n]), j1 = __ldg(&g_off[n + 1]);
            agg_node(n, j0, j1, t, o0, o1, lane);
        }
        sA.xsT[2 * lane][ln]     = o0;
        sA.xsT[2 * lane + 1][ln] = o1;
    }
    __syncthreads();

    // GEMM1: thread (ng = tid&15 -> nodes 4ng..+3, hg = tid>>4 -> hid 8hg..+7)
    int ng = tid & 15, hg = tid >> 4;
    ull acc[4][4];   // [node][hid-pair]
    {
        const ulonglong2* bp = (const ulonglong2*)(cb1 + layer * HIDD + 8 * hg);
        ulonglong2 b01 = bp[0], b23 = bp[1];
#pragma unroll
        for (int n = 0; n < 4; n++) {
            acc[n][0] = b01.x; acc[n][1] = b01.y;
            acc[n][2] = b23.x; acc[n][3] = b23.y;
        }
    }
#pragma unroll 4
    for (int k = 0; k < HD; k++) {
        float4 a = *(const float4*)&sA.xsT[k][4 * ng];
        ull a0 = f2pack(a.x, a.x), a1 = f2pack(a.y, a.y);
        ull a2 = f2pack(a.z, a.z), a3 = f2pack(a.w, a.w);
        const ulonglong2* wp = (const ulonglong2*)(&g_w1t[layer][k][8 * hg]);
        ulonglong2 w01 = wp[0], w23 = wp[1];
        acc[0][0] = ffma2(a0, w01.x, acc[0][0]); acc[0][1] = ffma2(a0, w01.y, acc[0][1]);
        acc[0][2] = ffma2(a0, w23.x, acc[0][2]); acc[0][3] = ffma2(a0, w23.y, acc[0][3]);
        acc[1][0] = ffma2(a1, w01.x, acc[1][0]); acc[1][1] = ffma2(a1, w01.y, acc[1][1]);
        acc[1][2] = ffma2(a1, w23.x, acc[1][2]); acc[1][3] = ffma2(a1, w23.y, acc[1][3]);
        acc[2][0] = ffma2(a2, w01.x, acc[2][0]); acc[2][1] = ffma2(a2, w01.y, acc[2][1]);
        acc[2][2] = ffma2(a2, w23.x, acc[2][2]); acc[2][3] = ffma2(a2, w23.y, acc[2][3]);
        acc[3][0] = ffma2(a3, w01.x, acc[3][0]); acc[3][1] = ffma2(a3, w01.y, acc[3][1]);
        acc[3][2] = ffma2(a3, w23.x, acc[3][2]); acc[3][3] = ffma2(a3, w23.y, acc[3][3]);
    }
    __syncthreads();   // all GEMM1 reads of xsT done before aliased writes

    // LN partials per node over this thread's 8 hidden values
#pragma unroll
    for (int n = 0; n < 4; n++) {
        ull sp = addf2(addf2(acc[n][0], acc[n][1]), addf2(acc[n][2], acc[n][3]));
        ull qp = ffma2(acc[n][0], acc[n][0],
                 ffma2(acc[n][1], acc[n][1],
                 ffma2(acc[n][2], acc[n][2],
                 ffma2(acc[n][3], acc[n][3], f2pack(0.0f, 0.0f)))));
        float sl, sh, ql, qh;
        f2unpack(sp, sl, sh); f2unpack(qp, ql, qh);
        sA.r.red[4 * ng + n][hg] = f2pack(sl + sh, ql + qh);
    }
    __syncthreads();
    if (tid < 64) {
        float s = 0.0f, s2 = 0.0f;
#pragma unroll
        for (int j = 0; j < 16; j++) {
            float a, b; f2unpack(sA.r.red[tid][j], a, b);
            s += a; s2 += b;
        }
        float mu = s * (1.0f / HIDD);
        float var = s2 * (1.0f / HIDD) - mu * mu;
        sA.r.murs[tid] = make_float2(mu, rsqrtf(var + 1e-5f));
    }
    __syncthreads();

    // normalize + gamma/beta + relu -> HT
    {
        float g8[8], b8[8];
        const float4* gp = (const float4*)(cg  + layer * HIDD + 8 * hg);
        const float4* bp = (const float4*)(cbn + layer * HIDD + 8 * hg);
        float4 gv0 = gp[0], gv1 = gp[1], bv0 = bp[0], bv1 = bp[1];
        g8[0] = gv0.x; g8[1] = gv0.y; g8[2] = gv0.z; g8[3] = gv0.w;
        g8[4] = gv1.x; g8[5] = gv1.y; g8[6] = gv1.z; g8[7] = gv1.w;
        b8[0] = bv0.x; b8[1] = bv0.y; b8[2] = bv0.z; b8[3] = bv0.w;
        b8[4] = bv1.x; b8[5] = bv1.y; b8[6] = bv1.z; b8[7] = bv1.w;
#pragma unroll
        for (int n = 0; n < 4; n++) {
            float2 mr = sA.r.murs[4 * ng + n];
            float v[8];
#pragma unroll
            for (int p = 0; p < 4; p++) f2unpack(acc[n][p], v[2 * p], v[2 * p + 1]);
#pragma unroll
            for (int h = 0; h < 8; h++) {
                float z = fmaxf((v[h] - mr.x) * mr.y * g8[h] + b8[h], 0.0f);
                HT[8 * hg + h][4 * ng + n] = z;
            }
        }
    }
    __syncthreads();

    // GEMM2: thread (ng -> nodes 4ng..+3, og = hg -> outputs 4og..+3)
    int og = hg;
    ull acc2[4][2];
    {
        const ulonglong2* bp = (const ulonglong2*)(cb2 + layer * HD + 4 * og);
        ulonglong2 bv = bp[0];
#pragma unroll
        for (int n = 0; n < 4; n++) { acc2[n][0] = bv.x; acc2[n][1] = bv.y; }
    }
#pragma unroll 4
    for (int k = 0; k < HIDD; k++) {
        float4 a = *(const float4*)&HT[k][4 * ng];
        ull a0 = f2pack(a.x, a.x), a1 = f2pack(a.y, a.y);
        ull a2 = f2pack(a.z, a.z), a3 = f2pack(a.w, a.w);
        ulonglong2 w = *(const ulonglong2*)(&g_w2t[layer][k][4 * og]);
        acc2[0][0] = ffma2(a0, w.x, acc2[0][0]); acc2[0][1] = ffma2(a0, w.y, acc2[0][1]);
        acc2[1][0] = ffma2(a1, w.x, acc2[1][0]); acc2[1][1] = ffma2(a1, w.y, acc2[1][1]);
        acc2[2][0] = ffma2(a2, w.x, acc2[2][0]); acc2[2][1] = ffma2(a2, w.y, acc2[2][1]);
        acc2[3][0] = ffma2(a3, w.x, acc2[3][0]); acc2[3][1] = ffma2(a3, w.y, acc2[3][1]);
    }
#pragma unroll
    for (int n = 0; n < 4; n++) {
        int node = nb + 4 * ng + n;
        if (node >= NN) continue;
        float4 r;
        f2unpack(acc2[n][0], r.x, r.y);
        f2unpack(acc2[n][1], r.z, r.w);
        float4* hp = (float4*)(g_h + (size_t)node * HD + 4 * og);
        if (resid) {
            float4 old = *hp;
            r.x += old.x; r.y += old.y; r.z += old.z; r.w += old.w;
        }
        *hp = r;
    }
}

// ---------------- final norm + global max pool ----------------
__global__ void k_final_pool(const float* __restrict__ lng, const float* __restrict__ lnb,
                             const int* __restrict__ batch) {
    int gid = blockIdx.x * blockDim.x + threadIdx.x;
    int n = gid >> 5, lane = gid & 31;
    if (n >= NN) return;
    float v0 = g_h[n * HD + lane], v1 = g_h[n * HD + lane + 32];
    float s = v0 + v1, s2 = v0 * v0 + v1 * v1;
    warp_reduce2(s, s2);
    float mu = s * (1.0f / HD);
    float var = s2 * (1.0f / HD) - mu * mu;
    float rs = rsqrtf(var + 1e-5f);
    float z0 = fmaxf((v0 - mu) * rs * lng[lane] + lnb[lane], 0.0f);
    float z1 = fmaxf((v1 - mu) * rs * lng[lane + 32] + lnb[lane + 32], 0.0f);
    int g = __ldg(batch + n);
    atomicMax(&g_pool[g * HD + lane],      fenc(z0));
    atomicMax(&g_pool[g * HD + lane + 32], fenc(z1));
}

// ---------------- readout ----------------
__global__ void k_readout(const float* __restrict__ ro_w, const float* __restrict__ ro_b,
                          float* __restrict__ out) {
    int g = threadIdx.x;
    if (g >= NG) return;
    float acc = ro_b[0];
#pragma unroll
    for (int f = 0; f < HD; f++)
        acc = fmaf(fdec(g_pool[g * HD + f]), ro_w[f], acc);
    out[g] = 1.0f / (1.0f + expf(-acc));
}

extern "C" void kernel_launch(void* const* d_in, const int* in_sizes, int n_in,
                              void* d_out, int out_size) {
    const float* x       = (const float*)d_in[0];
    const float* eattr   = (const float*)d_in[1];
    const float* ne_w    = (const float*)d_in[2];
    const float* ne_b    = (const float*)d_in[3];
    const float* ee_w1   = (const float*)d_in[4];
    const float* ee_b1   = (const float*)d_in[5];
    const float* ee_w2   = (const float*)d_in[6];
    const float* ee_b2   = (const float*)d_in[7];
    const float* conv_w1 = (const float*)d_in[8];
    const float* conv_b1 = (const float*)d_in[9];
    const float* conv_g  = (const float*)d_in[10];
    const float* conv_bn = (const float*)d_in[11];
    const float* conv_w2 = (const float*)d_in[12];
    const float* conv_b2 = (const float*)d_in[13];
    const float* conv_t  = (const float*)d_in[14];
    const float* ln_g    = (const float*)d_in[15];
    const float* ln_b    = (const float*)d_in[16];
    const float* ro_w    = (const float*)d_in[17];
    const float* ro_b    = (const float*)d_in[18];
    const int*   eidx    = (const int*)d_in[19];
    const int*   batch   = (const int*)d_in[20];
    const int* src = eidx;
    const int* dst = eidx + NE;
    float* out = (float*)d_out;

    // 0-2: CSR build (g_cnt zeroed by previous call's k_setup; zero-init on first call)
    k_hist<<<(NE + 255) / 256, 256>>>(dst);
    k_scan<<<1, 1024>>>();
    k_scatter<<<(NE + 255) / 256, 256>>>(src, dst);

    // 3: PROBE — verifies the reg/MLP fix under ncu (dead output, steady-state inputs)
    k_agg_probe<<<(NPROBE + 7) / 8, 256>>>(conv_t);

    // 4: edge MLP
    k_edge_mlp<<<NE / 128, 128>>>(eattr, ee_w1, ee_b1, ee_w2, ee_b2);

    // 5: fused setup
    k_setup<<<(NN + 7) / 8, 256>>>(x, ne_w, ne_b, conv_w1, conv_w2);

    // 6: layer 0 (gathers from xin snapshot written by setup)
    k_layer<<<(NN + 63) / 64, 256>>>(0, 0, conv_b1, conv_g, conv_bn, conv_b2, conv_t);

    // 7-10: layers 1..2
    for (int l = 1; l < NL; l++) {
        k_prep<<<(NN * 32 + 255) / 256, 256>>>(ln_g, ln_b, l);
        k_layer<<<(NN + 63) / 64, 256>>>(1, l, conv_b1, conv_g, conv_bn, conv_b2, conv_t);
    }

    // 11-12: pool + readout
    k_final_pool<<<(NN * 32 + 255) / 256, 256>>>(ln_g, ln_b, batch);
    k_readout<<<1, 64>>>(ro_w, ro_b, out);
}

// round 17
// speedup vs baseline: 1.0639x; 1.0639x over previous
#include <cuda_runtime.h>

#define NN   50000
#define NE   1200000
#define NG   64
#define FN   128
#define FE   32
#define HD   64
#define HIDD 128
#define NL   3
#define NPROBE 3125

typedef unsigned long long ull;

// ---------------- device scratch ----------------
__device__ __align__(16) float g_ea[(size_t)NE * HD];      // edge embeddings fp32, dst-sorted order
__device__ __align__(16) float g_h[NN * HD];               // node state
__device__ __align__(16) float g_xin[NN * HD];             // conv input (gather source)
__device__ __align__(16) float g_agg[NPROBE * HD];         // probe output (dead)
__device__ int  g_cnt[NN];                                 // in-degree histogram (zeroed by setup for next call)
__device__ int  g_off[NN + 1];                             // CSR offsets
__device__ int  g_cur[NN];                                 // running scatter cursor
__device__ int  g_srcp[NE];                                // src node per sorted slot
__device__ int  g_epos[NE];                                // sorted slot for edge e
__device__ unsigned int g_pool[NG * HD];                   // encoded max-pool
__device__ __align__(16) float g_w1t[NL][HD][HIDD];        // conv_w1^T  [l][k][j]
__device__ __align__(16) float g_w2t[NL][HIDD][HD];        // conv_w2^T  [l][j][o]

__device__ __forceinline__ unsigned fenc(float f) {
    unsigned u = __float_as_uint(f);
    return (u & 0x80000000u) ? ~u : (u | 0x80000000u);
}
__device__ __forceinline__ float fdec(unsigned u) {
    return (u & 0x80000000u) ? __uint_as_float(u & 0x7fffffffu) : __uint_as_float(~u);
}

__device__ __forceinline__ void warp_reduce2(float& s, float& s2) {
#pragma unroll
    for (int o = 16; o > 0; o >>= 1) {
        s  += __shfl_xor_sync(0xffffffffu, s,  o);
        s2 += __shfl_xor_sync(0xffffffffu, s2, o);
    }
}

// ---- packed f32x2 helpers (FFMA2 on sm_103a) ----
__device__ __forceinline__ ull f2pack(float lo, float hi) {
    ull r; asm("mov.b64 %0,{%1,%2};" : "=l"(r) : "f"(lo), "f"(hi)); return r;
}
__device__ __forceinline__ void f2unpack(ull v, float& lo, float& hi) {
    asm("mov.b64 {%0,%1},%2;" : "=f"(lo), "=f"(hi) : "l"(v));
}
__device__ __forceinline__ ull ffma2(ull a, ull b, ull c) {
    ull d; asm("fma.rn.f32x2 %0,%1,%2,%3;" : "=l"(d) : "l"(a), "l"(b), "l"(c)); return d;
}
__device__ __forceinline__ ull addf2(ull a, ull b) {
    ull d; asm("add.rn.f32x2 %0,%1,%2;" : "=l"(d) : "l"(a), "l"(b)); return d;
}

// ---------------- CSR build ----------------
__global__ void k_hist(const int* __restrict__ dst) {
    int e = blockIdx.x * blockDim.x + threadIdx.x;
    if (e < NE) atomicAdd(&g_cnt[dst[e]], 1);
}

__global__ void k_scan() {
    __shared__ int part[1024];
    int t = threadIdx.x;
    const int per = (NN + 1023) / 1024;   // 49
    int base = t * per;
    int s = 0;
#pragma unroll 4
    for (int i = 0; i < per; i++) {
        int b = base + i;
        if (b < NN) s += g_cnt[b];
    }
    part[t] = s;
    __syncthreads();
    for (int o = 1; o < 1024; o <<= 1) {
        int v = (t >= o) ? part[t - o] : 0;
        __syncthreads();
        part[t] += v;
        __syncthreads();
    }
    int run = part[t] - s;   // exclusive prefix
    for (int i = 0; i < per; i++) {
        int b = base + i;
        if (b < NN) {
            g_off[b] = run;
            g_cur[b] = run;
            run += g_cnt[b];
        }
    }
    if (t == 1023) g_off[NN] = part[1023];
}

__global__ void k_scatter(const int* __restrict__ src, const int* __restrict__ dst) {
    int e = blockIdx.x * blockDim.x + threadIdx.x;
    if (e >= NE) return;
    int d = dst[e];
    int p = atomicAdd(&g_cur[d], 1);
    g_srcp[p] = src[e];
    g_epos[e] = p;
}

// ---------------- aggregation core: half-warp-per-edge, LDG.128, 4-pair pipeline ----------
// lanes 0-15 process even edges, 16-31 odd edges; lane owns features 4q..4q+3 (q=lane&15).
// 8 LDG.128 in flight per warp = 1KB (2x the float2 version at identical queue occupancy).
// Result (after shfl_xor(16) combine): ALL lanes hold {o[0..3]} for features 4q..4q+3.
__device__ __forceinline__ void agg_node4(int n, int j0, int j1, float t,
                                          float4& ov, int lane) {
    const float4* ea4  = (const float4*)g_ea;     // 16 float4 per edge row
    const float4* xin4 = (const float4*)g_xin;
    int nk = j1 - j0;
    int half = lane >> 4;
    int q = lane & 15;
    float d0 = 0.f, d1 = 0.f, d2 = 0.f, d3 = 0.f;
    float w0 = 0.f, w1 = 0.f, w2 = 0.f, w3 = 0.f;

#define AGG4(EV, XV, VF)                                                     \
    {                                                                        \
        float m0 = fmaxf(XV.x + EV.x, 0.0f) + 1e-7f;                         \
        float m1 = fmaxf(XV.y + EV.y, 0.0f) + 1e-7f;                         \
        float m2 = fmaxf(XV.z + EV.z, 0.0f) + 1e-7f;                         \
        float m3 = fmaxf(XV.w + EV.w, 0.0f) + 1e-7f;                         \
        float a0 = __expf(m0 * t) * VF, a1 = __expf(m1 * t) * VF;            \
        float a2 = __expf(m2 * t) * VF, a3 = __expf(m3 * t) * VF;            \
        d0 += a0; d1 += a1; d2 += a2; d3 += a3;                              \
        w0 = fmaf(m0, a0, w0); w1 = fmaf(m1, a1, w1);                        \
        w2 = fmaf(m2, a2, w2); w3 = fmaf(m3, a3, w3);                        \
    }

    for (int base = 0; base < nk; base += 32) {
        int cn = nk - base; if (cn > 32) cn = 32;
        int sv = (lane < cn) ? __ldg(&g_srcp[j0 + base + lane]) : 0;
        int kk = 0;
        for (; kk + 8 <= cn; kk += 8) {
            int s[4];
#pragma unroll
            for (int u = 0; u < 4; u++)
                s[u] = __shfl_sync(0xffffffffu, sv, kk + 2 * u + half);
            float4 ev[4], xv[4];
            size_t eb = (size_t)(j0 + base + kk + half) * 16 + q;
#pragma unroll
            for (int u = 0; u < 4; u++) ev[u] = __ldcs(ea4 + eb + (size_t)(2 * u) * 16);
#pragma unroll
            for (int u = 0; u < 4; u++) xv[u] = __ldg(xin4 + (size_t)s[u] * 16 + q);
#pragma unroll
            for (int u = 0; u < 4; u++) AGG4(ev[u], xv[u], 1.0f)
        }
        for (; kk < cn; kk += 2) {
            int idx = kk + half;
            float vf = (idx < cn) ? 1.0f : 0.0f;
            int pick = (idx < cn) ? idx : kk;
            int s = __shfl_sync(0xffffffffu, sv, pick);
            float4 ev = __ldcs(ea4 + (size_t)(j0 + base + pick) * 16 + q);
            float4 xv = __ldg(xin4 + (size_t)s * 16 + q);
            AGG4(ev, xv, vf)
        }
    }
#undef AGG4

    // combine even/odd halves (lane L <-> L+16 hold same features)
    d0 += __shfl_xor_sync(0xffffffffu, d0, 16);
    d1 += __shfl_xor_sync(0xffffffffu, d1, 16);
    d2 += __shfl_xor_sync(0xffffffffu, d2, 16);
    d3 += __shfl_xor_sync(0xffffffffu, d3, 16);
    w0 += __shfl_xor_sync(0xffffffffu, w0, 16);
    w1 += __shfl_xor_sync(0xffffffffu, w1, 16);
    w2 += __shfl_xor_sync(0xffffffffu, w2, 16);
    w3 += __shfl_xor_sync(0xffffffffu, w3, 16);

    float4 xs = xin4[(size_t)n * 16 + q];
    ov.x = w0 / (d0 + 1e-16f) + xs.x;
    ov.y = w1 / (d1 + 1e-16f) + xs.y;
    ov.z = w2 / (d2 + 1e-16f) + xs.z;
    ov.w = w3 / (d3 + 1e-16f) + xs.w;
}

// ---------------- PROBE: agg only, 1/16 of nodes, dead output (ncu lands here) ----------------
__global__ void __launch_bounds__(256, 3) k_agg_probe(const float* __restrict__ ct) {
    int warp = threadIdx.x >> 5, lane = threadIdx.x & 31;
    int n = blockIdx.x * 8 + warp;
    if (n >= NPROBE) return;
    float t = __ldg(ct + 1);
    int j0 = __ldg(&g_off[n]), j1 = __ldg(&g_off[n + 1]);
    float4 ov;
    agg_node4(n, j0, j1, t, ov, lane);
    if (lane < 16)
        ((float4*)g_agg)[(size_t)n * 16 + (lane & 15)] = ov;
}

// ---------------- fused setup: transpose + embed (h AND xin) + zero cnt/pool ----------------
__global__ void __launch_bounds__(256) k_setup(
        const float* __restrict__ x, const float* __restrict__ ne_w,
        const float* __restrict__ ne_b,
        const float* __restrict__ cw1, const float* __restrict__ cw2) {
    int gid = blockIdx.x * blockDim.x + threadIdx.x;
    if (gid < NN) g_cnt[gid] = 0;                               // for NEXT call's hist
    else if (gid < NN + NG * HD) g_pool[gid - NN] = 0u;
    else if (gid < NN + NG * HD + NL * HIDD * HD) {
        int i = gid - NN - NG * HD;
        int l = i / (HIDD * HD), r = i % (HIDD * HD);
        int j = r / HD, k = r % HD;
        g_w1t[l][k][j] = cw1[i];
    } else if (gid < NN + NG * HD + 2 * NL * HIDD * HD) {
        int i = gid - NN - NG * HD - NL * HIDD * HD;
        int l = i / (HD * HIDD), r = i % (HD * HIDD);
        int o = r / HIDD, j = r % HIDD;
        g_w2t[l][j][o] = cw2[i];
    }

    __shared__ float wst[FN][HD];
    __shared__ float xsh[8][FN];
    for (int idx = threadIdx.x; idx < FN * HD; idx += blockDim.x) {
        int j = idx & (HD - 1), k = idx >> 6;
        wst[k][j] = ne_w[j * FN + k];
    }
    __syncthreads();
    int warp = threadIdx.x >> 5, lane = threadIdx.x & 31;
    int n = blockIdx.x * 8 + warp;
    if (n >= NN) return;
    ((float4*)xsh[warp])[lane] = ((const float4*)x)[(size_t)n * (FN / 4) + lane];
    __syncwarp();
    float acc0 = ne_b[lane], acc1 = ne_b[lane + 32];
#pragma unroll
    for (int k = 0; k < FN; k++) {
        float xk = xsh[warp][k];
        acc0 = fmaf(xk, wst[k][lane], acc0);
        acc1 = fmaf(xk, wst[k][lane + 32], acc1);
    }
    g_h[n * HD + lane]        = acc0;
    g_h[n * HD + lane + 32]   = acc1;
    g_xin[n * HD + lane]      = acc0;
    g_xin[n * HD + lane + 32] = acc1;
}

// ---------------- edge MLP: per-edge GEMM1 + tiled GEMM2 + staged coalesced scatter-store ----
// (R15-proven version.) 128 threads = 128 edges per block; NE divisible by 128.
__global__ void __launch_bounds__(128) k_edge_mlp(
        const float* __restrict__ attr,
        const float* __restrict__ w1, const float* __restrict__ b1,
        const float* __restrict__ w2, const float* __restrict__ b2) {
    __shared__ __align__(16) ull w1p[FE][FE / 2];     // 4KB
    __shared__ __align__(16) ull w2p[FE][HD / 2];     // 8KB
    __shared__ __align__(16) ull b1p[FE / 2];
    __shared__ __align__(16) ull b2p[HD / 2];
    __shared__ int posb[128];
    __shared__ __align__(16) float ubuf[FE * 128];    // 16KB: hT, then aliased as stage
    float (*hT)[128] = (float(*)[128])ubuf;
    ull* stage = (ull*)ubuf;                          // quarter: 32 rows x 33 ull (8.4KB)

    int tid = threadIdx.x;
    for (int i = tid; i < FE * FE / 2; i += blockDim.x) {
        int k = i / (FE / 2), j2 = i % (FE / 2);
        w1p[k][j2] = f2pack(w1[(2 * j2) * FE + k], w1[(2 * j2 + 1) * FE + k]);
    }
    for (int i = tid; i < FE * HD / 2; i += blockDim.x) {
        int j = i / (HD / 2), i2 = i % (HD / 2);
        w2p[j][i2] = f2pack(w2[(2 * i2) * FE + j], w2[(2 * i2 + 1) * FE + j]);
    }
    if (tid < FE / 2) b1p[tid] = f2pack(b1[2 * tid], b1[2 * tid + 1]);
    if (tid >= 64 && tid < 64 + HD / 2) {
        int i2 = tid - 64;
        b2p[i2] = f2pack(b2[2 * i2], b2[2 * i2 + 1]);
    }
    int eb = blockIdx.x * 128;
    posb[tid] = __ldg(&g_epos[eb + tid]);
    __syncthreads();

    int e = eb + tid;

    // --- GEMM1 (per edge, register-resident) ---
    float av[FE];
    const float4* in4 = (const float4*)(attr + (size_t)e * FE);
#pragma unroll
    for (int k4 = 0; k4 < FE / 4; k4++) {
        float4 v = __ldcs(in4 + k4);
        av[k4 * 4 + 0] = v.x; av[k4 * 4 + 1] = v.y;
        av[k4 * 4 + 2] = v.z; av[k4 * 4 + 3] = v.w;
    }
    ull hp[FE / 2];
#pragma unroll
    for (int j2 = 0; j2 < FE / 2; j2++) hp[j2] = b1p[j2];
#pragma unroll
    for (int k = 0; k < FE; k++) {
        ull vkk = f2pack(av[k], av[k]);
#pragma unroll
        for (int j4 = 0; j4 < FE / 4; j4++) {
            ulonglong2 w = *(const ulonglong2*)&w1p[k][2 * j4];
            hp[2 * j4]     = ffma2(vkk, w.x, hp[2 * j4]);
            hp[2 * j4 + 1] = ffma2(vkk, w.y, hp[2 * j4 + 1]);
        }
    }
    // relu -> hT columns (conflict-free: bank = edge lane)
#pragma unroll
    for (int j2 = 0; j2 < FE / 2; j2++) {
        float lo, hi; f2unpack(hp[j2], lo, hi);
        hT[2 * j2][tid]     = fmaxf(lo, 0.0f);
        hT[2 * j2 + 1][tid] = fmaxf(hi, 0.0f);
    }
    __syncthreads();

    // --- GEMM2 (tiled): thread (eg = tid&31 -> edges eg+32n, og = tid>>5 -> outputs 16og..+15)
    int eg = tid & 31, og = tid >> 5;
    ull acc[4][8];   // [n -> edge eg+32n][output pair]
    {
        ulonglong2 bA = *(const ulonglong2*)&b2p[8 * og];
        ulonglong2 bB = *(const ulonglong2*)&b2p[8 * og + 2];
        ulonglong2 bC = *(const ulonglong2*)&b2p[8 * og + 4];
        ulonglong2 bD = *(const ulonglong2*)&b2p[8 * og + 6];
#pragma unroll
        for (int n = 0; n < 4; n++) {
            acc[n][0] = bA.x; acc[n][1] = bA.y; acc[n][2] = bB.x; acc[n][3] = bB.y;
            acc[n][4] = bC.x; acc[n][5] = bC.y; acc[n][6] = bD.x; acc[n][7] = bD.y;
        }
    }
#pragma unroll 2
    for (int k = 0; k < FE; k++) {
        float h0 = hT[k][eg], h1 = hT[k][eg + 32];
        float h2 = hT[k][eg + 64], h3 = hT[k][eg + 96];
        ull a0 = f2pack(h0, h0), a1 = f2pack(h1, h1);
        ull a2 = f2pack(h2, h2), a3 = f2pack(h3, h3);
        ulonglong2 wA = *(const ulonglong2*)&w2p[k][8 * og];
        ulonglong2 wB = *(const ulonglong2*)&w2p[k][8 * og + 2];
        ulonglong2 wC = *(const ulonglong2*)&w2p[k][8 * og + 4];
        ulonglong2 wD = *(const ulonglong2*)&w2p[k][8 * og + 6];
#define G2ROW(n, an)                                                     \
        acc[n][0] = ffma2(an, wA.x, acc[n][0]);                          \
        acc[n][1] = ffma2(an, wA.y, acc[n][1]);                          \
        acc[n][2] = ffma2(an, wB.x, acc[n][2]);                          \
        acc[n][3] = ffma2(an, wB.y, acc[n][3]);                          \
        acc[n][4] = ffma2(an, wC.x, acc[n][4]);                          \
        acc[n][5] = ffma2(an, wC.y, acc[n][5]);                          \
        acc[n][6] = ffma2(an, wD.x, acc[n][6]);                          \
        acc[n][7] = ffma2(an, wD.y, acc[n][7]);
        G2ROW(0, a0) G2ROW(1, a1) G2ROW(2, a2) G2ROW(3, a3)
#undef G2ROW
    }
    __syncthreads();   // GEMM2 hT reads complete before stage aliases ubuf

    // --- staged coalesced scatter-store: 4 quarters of 32 edges ---
#pragma unroll
    for (int qd = 0; qd < 4; qd++) {
#pragma unroll
        for (int q = 0; q < 8; q++)
            stage[(size_t)eg * 33 + 8 * og + q] = acc[qd][q];
        __syncthreads();
#pragma unroll
        for (int p = 0; p < 4; p++) {
            int le = p * 8 + (tid >> 4);   // 0..31
            int ch = tid & 15;             // 16B chunk within row
            ull a = stage[(size_t)le * 33 + 2 * ch];
            ull b = stage[(size_t)le * 33 + 2 * ch + 1];
            int pos = posb[32 * qd + le];
            *(ulonglong2*)(g_ea + (size_t)pos * HD + 4 * ch) = make_ulonglong2(a, b);
        }
        __syncthreads();
    }
}

// ---------------- pre-norm: xin = relu(LN(h)) ----------------
__global__ void k_prep(const float* __restrict__ lng, const float* __restrict__ lnb, int layer) {
    int gid = blockIdx.x * blockDim.x + threadIdx.x;
    int n = gid >> 5, lane = gid & 31;
    if (n >= NN) return;
    float v0 = g_h[n * HD + lane], v1 = g_h[n * HD + lane + 32];
    float s = v0 + v1, s2 = v0 * v0 + v1 * v1;
    warp_reduce2(s, s2);
    float mu = s * (1.0f / HD);
    float var = s2 * (1.0f / HD) - mu * mu;
    float rs = rsqrtf(var + 1e-5f);
    const float* g = lng + layer * HD;
    const float* b = lnb + layer * HD;
    g_xin[n * HD + lane]      = fmaxf((v0 - mu) * rs * g[lane] + b[lane], 0.0f);
    g_xin[n * HD + lane + 32] = fmaxf((v1 - mu) * rs * g[lane + 32] + b[lane + 32], 0.0f);
}

// ---------------- fused layer: 64-node tile, agg + block-cooperative MLP ----------------
union SmemA {
    float xsT[HD][64];                                   // [feat][local node]
    struct { ull red[64][17]; float2 murs[64]; } r;      // aliased AFTER GEMM1 reads done
};

__global__ void __launch_bounds__(256, 3) k_layer(
                        int resid, int layer,
                        const float* __restrict__ cb1, const float* __restrict__ cg,
                        const float* __restrict__ cbn, const float* __restrict__ cb2,
                        const float* __restrict__ ct) {
    __shared__ SmemA sA;
    __shared__ float HT[HIDD][64];                       // [hid][local node]
    int tid = threadIdx.x;
    int warp = tid >> 5, lane = tid & 31;
    int nb = blockIdx.x * 64;
    float t = __ldg(ct + layer);

    // Phase A: 8 warps x 8 nodes, half-warp-per-edge agg core; transposed store
    for (int q = 0; q < 8; q++) {
        int ln = warp * 8 + q;
        int n = nb + ln;
        float4 ov = make_float4(0.f, 0.f, 0.f, 0.f);
        if (n < NN) {
            int j0 = __ldg(&g_off[n]), j1 = __ldg(&g_off[n + 1]);
            agg_node4(n, j0, j1, t, ov, lane);
        }
        if (lane < 16) {
            int fq = lane & 15;
            sA.xsT[4 * fq + 0][ln] = ov.x;
            sA.xsT[4 * fq + 1][ln] = ov.y;
            sA.xsT[4 * fq + 2][ln] = ov.z;
            sA.xsT[4 * fq + 3][ln] = ov.w;
        }
    }
    __syncthreads();

    // GEMM1: thread (ng = tid&15 -> nodes 4ng..+3, hg = tid>>4 -> hid 8hg..+7)
    int ng = tid & 15, hg = tid >> 4;
    ull acc[4][4];   // [node][hid-pair]
    {
        const ulonglong2* bp = (const ulonglong2*)(cb1 + layer * HIDD + 8 * hg);
        ulonglong2 b01 = bp[0], b23 = bp[1];
#pragma unroll
        for (int n = 0; n < 4; n++) {
            acc[n][0] = b01.x; acc[n][1] = b01.y;
            acc[n][2] = b23.x; acc[n][3] = b23.y;
        }
    }
#pragma unroll 4
    for (int k = 0; k < HD; k++) {
        float4 a = *(const float4*)&sA.xsT[k][4 * ng];
        ull a0 = f2pack(a.x, a.x), a1 = f2pack(a.y, a.y);
        ull a2 = f2pack(a.z, a.z), a3 = f2pack(a.w, a.w);
        const ulonglong2* wp = (const ulonglong2*)(&g_w1t[layer][k][8 * hg]);
        ulonglong2 w01 = wp[0], w23 = wp[1];
        acc[0][0] = ffma2(a0, w01.x, acc[0][0]); acc[0][1] = ffma2(a0, w01.y, acc[0][1]);
        acc[0][2] = ffma2(a0, w23.x, acc[0][2]); acc[0][3] = ffma2(a0, w23.y, acc[0][3]);
        acc[1][0] = ffma2(a1, w01.x, acc[1][0]); acc[1][1] = ffma2(a1, w01.y, acc[1][1]);
        acc[1][2] = ffma2(a1, w23.x, acc[1][2]); acc[1][3] = ffma2(a1, w23.y, acc[1][3]);
        acc[2][0] = ffma2(a2, w01.x, acc[2][0]); acc[2][1] = ffma2(a2, w01.y, acc[2][1]);
        acc[2][2] = ffma2(a2, w23.x, acc[2][2]); acc[2][3] = ffma2(a2, w23.y, acc[2][3]);
        acc[3][0] = ffma2(a3, w01.x, acc[3][0]); acc[3][1] = ffma2(a3, w01.y, acc[3][1]);
        acc[3][2] = ffma2(a3, w23.x, acc[3][2]); acc[3][3] = ffma2(a3, w23.y, acc[3][3]);
    }
    __syncthreads();   // all GEMM1 reads of xsT done before aliased writes

    // LN partials per node over this thread's 8 hidden values
#pragma unroll
    for (int n = 0; n < 4; n++) {
        ull sp = addf2(addf2(acc[n][0], acc[n][1]), addf2(acc[n][2], acc[n][3]));
        ull qp = ffma2(acc[n][0], acc[n][0],
                 ffma2(acc[n][1], acc[n][1],
                 ffma2(acc[n][2], acc[n][2],
                 ffma2(acc[n][3], acc[n][3], f2pack(0.0f, 0.0f)))));
        float sl, sh, ql, qh;
        f2unpack(sp, sl, sh); f2unpack(qp, ql, qh);
        sA.r.red[4 * ng + n][hg] = f2pack(sl + sh, ql + qh);
    }
    __syncthreads();
    if (tid < 64) {
        float s = 0.0f, s2 = 0.0f;
#pragma unroll
        for (int j = 0; j < 16; j++) {
            float a, b; f2unpack(sA.r.red[tid][j], a, b);
            s += a; s2 += b;
        }
        float mu = s * (1.0f / HIDD);
        float var = s2 * (1.0f / HIDD) - mu * mu;
        sA.r.murs[tid] = make_float2(mu, rsqrtf(var + 1e-5f));
    }
    __syncthreads();

    // normalize + gamma/beta + relu -> HT
    {
        float g8[8], b8[8];
        const float4* gp = (const float4*)(cg  + layer * HIDD + 8 * hg);
        const float4* bp = (const float4*)(cbn + layer * HIDD + 8 * hg);
        float4 gv0 = gp[0], gv1 = gp[1], bv0 = bp[0], bv1 = bp[1];
        g8[0] = gv0.x; g8[1] = gv0.y; g8[2] = gv0.z; g8[3] = gv0.w;
        g8[4] = gv1.x; g8[5] = gv1.y; g8[6] = gv1.z; g8[7] = gv1.w;
        b8[0] = bv0.x; b8[1] = bv0.y; b8[2] = bv0.z; b8[3] = bv0.w;
        b8[4] = bv1.x; b8[5] = bv1.y; b8[6] = bv1.z; b8[7] = bv1.w;
#pragma unroll
        for (int n = 0; n < 4; n++) {
            float2 mr = sA.r.murs[4 * ng + n];
            float v[8];
#pragma unroll
            for (int p = 0; p < 4; p++) f2unpack(acc[n][p], v[2 * p], v[2 * p + 1]);
#pragma unroll
            for (int h = 0; h < 8; h++) {
                float z = fmaxf((v[h] - mr.x) * mr.y * g8[h] + b8[h], 0.0f);
                HT[8 * hg + h][4 * ng + n] = z;
            }
        }
    }
    __syncthreads();

    // GEMM2: thread (ng -> nodes 4ng..+3, og = hg -> outputs 4og..+3)
    int og = hg;
    ull acc2[4][2];
    {
        const ulonglong2* bp = (const ulonglong2*)(cb2 + layer * HD + 4 * og);
        ulonglong2 bv = bp[0];
#pragma unroll
        for (int n = 0; n < 4; n++) { acc2[n][0] = bv.x; acc2[n][1] = bv.y; }
    }
#pragma unroll 4
    for (int k = 0; k < HIDD; k++) {
        float4 a = *(const float4*)&HT[k][4 * ng];
        ull a0 = f2pack(a.x, a.x), a1 = f2pack(a.y, a.y);
        ull a2 = f2pack(a.z, a.z), a3 = f2pack(a.w, a.w);
        ulonglong2 w = *(const ulonglong2*)(&g_w2t[layer][k][4 * og]);
        acc2[0][0] = ffma2(a0, w.x, acc2[0][0]); acc2[0][1] = ffma2(a0, w.y, acc2[0][1]);
        acc2[1][0] = ffma2(a1, w.x, acc2[1][0]); acc2[1][1] = ffma2(a1, w.y, acc2[1][1]);
        acc2[2][0] = ffma2(a2, w.x, acc2[2][0]); acc2[2][1] = ffma2(a2, w.y, acc2[2][1]);
        acc2[3][0] = ffma2(a3, w.x, acc2[3][0]); acc2[3][1] = ffma2(a3, w.y, acc2[3][1]);
    }
#pragma unroll
    for (int n = 0; n < 4; n++) {
        int node = nb + 4 * ng + n;
        if (node >= NN) continue;
        float4 r;
        f2unpack(acc2[n][0], r.x, r.y);
        f2unpack(acc2[n][1], r.z, r.w);
        float4* hp = (float4*)(g_h + (size_t)node * HD + 4 * og);
        if (resid) {
            float4 old = *hp;
            r.x += old.x; r.y += old.y; r.z += old.z; r.w += old.w;
        }
        *hp = r;
    }
}

// ---------------- final norm + global max pool ----------------
__global__ void k_final_pool(const float* __restrict__ lng, const float* __restrict__ lnb,
                             const int* __restrict__ batch) {
    int gid = blockIdx.x * blockDim.x + threadIdx.x;
    int n = gid >> 5, lane = gid & 31;
    if (n >= NN) return;
    float v0 = g_h[n * HD + lane], v1 = g_h[n * HD + lane + 32];
    float s = v0 + v1, s2 = v0 * v0 + v1 * v1;
    warp_reduce2(s, s2);
    float mu = s * (1.0f / HD);
    float var = s2 * (1.0f / HD) - mu * mu;
    float rs = rsqrtf(var + 1e-5f);
    float z0 = fmaxf((v0 - mu) * rs * lng[lane] + lnb[lane], 0.0f);
    float z1 = fmaxf((v1 - mu) * rs * lng[lane + 32] + lnb[lane + 32], 0.0f);
    int g = __ldg(batch + n);
    atomicMax(&g_pool[g * HD + lane],      fenc(z0));
    atomicMax(&g_pool[g * HD + lane + 32], fenc(z1));
}

// ---------------- readout ----------------
__global__ void k_readout(const float* __restrict__ ro_w, const float* __restrict__ ro_b,
                          float* __restrict__ out) {
    int g = threadIdx.x;
    if (g >= NG) return;
    float acc = ro_b[0];
#pragma unroll
    for (int f = 0; f < HD; f++)
        acc = fmaf(fdec(g_pool[g * HD + f]), ro_w[f], acc);
    out[g] = 1.0f / (1.0f + expf(-acc));
}

extern "C" void kernel_launch(void* const* d_in, const int* in_sizes, int n_in,
                              void* d_out, int out_size) {
    const float* x       = (const float*)d_in[0];
    const float* eattr   = (const float*)d_in[1];
    const float* ne_w    = (const float*)d_in[2];
    const float* ne_b    = (const float*)d_in[3];
    const float* ee_w1   = (const float*)d_in[4];
    const float* ee_b1   = (const float*)d_in[5];
    const float* ee_w2   = (const float*)d_in[6];
    const float* ee_b2   = (const float*)d_in[7];
    const float* conv_w1 = (const float*)d_in[8];
    const float* conv_b1 = (const float*)d_in[9];
    const float* conv_g  = (const float*)d_in[10];
    const float* conv_bn = (const float*)d_in[11];
    const float* conv_w2 = (const float*)d_in[12];
    const float* conv_b2 = (const float*)d_in[13];
    const float* conv_t  = (const float*)d_in[14];
    const float* ln_g    = (const float*)d_in[15];
    const float* ln_b    = (const float*)d_in[16];
    const float* ro_w    = (const float*)d_in[17];
    const float* ro_b    = (const float*)d_in[18];
    const int*   eidx    = (const int*)d_in[19];
    const int*   batch   = (const int*)d_in[20];
    const int* src = eidx;
    const int* dst = eidx + NE;
    float* out = (float*)d_out;

    // 0-2: CSR build (g_cnt zeroed by previous call's k_setup; zero-init on first call)
    k_hist<<<(NE + 255) / 256, 256>>>(dst);
    k_scan<<<1, 1024>>>();
    k_scatter<<<(NE + 255) / 256, 256>>>(src, dst);

    // 3: PROBE — measures the float4 agg core under ncu (dead output, steady-state inputs)
    k_agg_probe<<<(NPROBE + 7) / 8, 256>>>(conv_t);

    // 4: edge MLP
    k_edge_mlp<<<NE / 128, 128>>>(eattr, ee_w1, ee_b1, ee_w2, ee_b2);

    // 5: fused setup
    k_setup<<<(NN + 7) / 8, 256>>>(x, ne_w, ne_b, conv_w1, conv_w2);

    // 6: layer 0 (gathers from xin snapshot written by setup)
    k_layer<<<(NN + 63) / 64, 256>>>(0, 0, conv_b1, conv_g, conv_bn, conv_b2, conv_t);

    // 7-10: layers 1..2
    for (int l = 1; l < NL; l++) {
        k_prep<<<(NN * 32 + 255) / 256, 256>>>(ln_g, ln_b, l);
        k_layer<<<(NN + 63) / 64, 256>>>(1, l, conv_b1, conv_g, conv_bn, conv_b2, conv_t);
    }

    // 11-12: pool + readout
    k_final_pool<<<(NN * 32 + 255) / 256, 256>>>(ln_g, ln_b, batch);
    k_readout<<<1, 64>>>(ro_w, ro_b, out);
}